// round 6
// baseline (speedup 1.0000x reference)
#include <cuda_runtime.h>
#include <math.h>

// ---------------------------------------------------------------------------
// CombinedLoss: 0.5*mean|o-t| + 0.5*mean|CWT(o)-CWT(t)| (real morlet, 36 widths)
// CWT(o)-CWT(t) = CWT(d), d=o-t.  'same' conv with reversed kernel ==
// correlation with un-reversed morlet:
//   conv_w[i] = sum_{p=0}^{10w-1} mor_w[p] * d[i + p - 5w]   (zero padded)
// Round 6: taps as FFMA immediates (rt_SMSP=1) via per-width constexpr arrays.
// Constexpr FP hygiene: early-break all Taylor loops before terms go subnormal.
// ---------------------------------------------------------------------------

#define L_TOTAL   262144
#define THREADS   128
#define RBLK      10
#define TILE      (THREADS * RBLK)                // 1280
#define NBX       ((L_TOTAL + TILE - 1) / TILE)   // 205
#define SD_DECL   (TILE + 2 * 180 + 20)           // 1660 (pad for +13 prefetch)

__device__ float g_cwt_part[4 * NBX];
__device__ float g_wave_part[NBX];

__constant__ int c_H[4] = {90, 126, 156, 180};    // 5*(w1-1) per group

// ======================= constexpr morlet coefficients ======================
__host__ __device__ constexpr double cabs_(double v) { return v < 0.0 ? -v : v; }

__host__ __device__ constexpr double cexp_(double xx) {
    if (xx < -120.0) return 0.0;   // only ew for w>=16; |rel effect| < 1e-49
    const double LN2_HI = 6.93147180369123816490e-01;
    const double LN2_LO = 1.90821492927058770002e-10;
    const double INV_LN2 = 1.44269504088896338700e+00;
    double nd = xx * INV_LN2;
    int n = (int)(nd >= 0.0 ? nd + 0.5 : nd - 0.5);
    double r = (xx - (double)n * LN2_HI) - (double)n * LN2_LO;
    double term = 1.0, sum = 1.0;
    for (int i = 1; i <= 18; ++i) {
        term *= r / (double)i;
        sum += term;
        if (cabs_(term) < 1e-60) break;            // converged; avoid underflow
    }
    // 2^n by squaring; never compute an unused square (avoids subnormals)
    double p = 1.0, b = (n < 0) ? 0.5 : 2.0;
    int m = (n < 0) ? -n : n;
    while (m) {
        if (m & 1) p *= b;
        m >>= 1;
        if (m) b *= b;
    }
    return sum * p;
}
__host__ __device__ constexpr double ccos_(double xx) {
    const double PIO2_1  = 1.57079632673412561417e+00;
    const double PIO2_1t = 6.07710050650619224932e-11;
    double ax = xx < 0.0 ? -xx : xx;               // cos is even
    int q = (int)(ax * 0.63661977236758134308 + 0.5);
    double r = (ax - (double)q * PIO2_1) - (double)q * PIO2_1t;
    double r2 = r * r;
    double cs = 1.0, tc = 1.0;
    for (int i = 1; i <= 10; ++i) {
        tc *= -r2 / (double)((2 * i - 1) * (2 * i));
        cs += tc;
        if (cabs_(tc) < 1e-60) break;              // avoid subnormal terms
    }
    double sn = r, ts = r;
    for (int i = 1; i <= 10; ++i) {
        ts *= -r2 / (double)((2 * i) * (2 * i + 1));
        sn += ts;
        if (cabs_(ts) < 1e-60) break;              // avoid subnormal terms
    }
    int quad = q & 3;
    return quad == 0 ? cs : quad == 1 ? -sn : quad == 2 ? -cs : sn;
}
__host__ __device__ constexpr double morlet_tap(int w, int p) {
    const double TWO_PI = 6.28318530717958647692;
    const double PI_M025 = 0.75112554446494248286;   // pi^(-1/4)
    int N = 10 * w;
    double step = (2.0 * TWO_PI) / (double)(N - 1);
    double x = -TWO_PI + (double)p * step;
    double ew = cexp_(-0.5 * (double)(w * w));
    return (ccos_((double)w * x) - ew) * cexp_(-0.5 * x * x) * PI_M025;
}

// Per-width constexpr tap table.
template<int W>
struct Ker { float k[10 * W]; };

template<int W>
__host__ __device__ constexpr Ker<W> make_ker() {
    Ker<W> t{};
    for (int p = 0; p < 10 * W; ++p) t.k[p] = (float)morlet_tap(W, p);
    return t;
}

// ============================ unrolled tap engine ===========================
template<int W>
__device__ __forceinline__ float do_width(const float* __restrict__ sd,
                                          int base, int gi0) {
    constexpr int N = 10 * W;
    constexpr Ker<W> KT = make_ker<W>();
    const int s0 = base - 5 * W;                     // >= 0 by construction

    float x[13], acc[RBLK];
    #pragma unroll
    for (int j = 0; j < 13; ++j) x[j] = sd[s0 + j];
    #pragma unroll
    for (int r = 0; r < RBLK; ++r) acc[r] = 0.f;

    #pragma unroll
    for (int p = 0; p < N; ++p) {
        const float k = KT.k[p];                     // compile-time constant
        #pragma unroll
        for (int r = 0; r < RBLK; ++r)
            acc[r] = fmaf(k, x[(p + r) % 13], acc[r]);
        x[p % 13] = sd[s0 + p + 13];                 // refill, used at tap p+4
    }

    float s = 0.f;
    #pragma unroll
    for (int r = 0; r < RBLK; ++r)
        if (gi0 + r < L_TOTAL) s += fabsf(acc[r]);
    return s;
}

template<int W0, int W1>
__device__ __forceinline__ float do_group(const float* __restrict__ sd,
                                          int base, int gi0) {
    if constexpr (W0 >= W1) { return 0.f; }
    else { return do_width<W0>(sd, base, gi0) + do_group<W0 + 1, W1>(sd, base, gi0); }
}

__device__ __forceinline__ float warp_sum(float v) {
    #pragma unroll
    for (int o = 16; o > 0; o >>= 1) v += __shfl_xor_sync(0xFFFFFFFFu, v, o);
    return v;
}

// ---------------------------------------------------------------------------
__global__ void __launch_bounds__(THREADS)
cwt_kernel(const float* __restrict__ o, const float* __restrict__ t) {
    __shared__ float sd[SD_DECL];
    __shared__ float s_red[8];

    const int gy = blockIdx.y;
    const int H  = c_H[gy];
    const int tile0 = blockIdx.x * TILE;
    const int tid = threadIdx.x;

    // Load diff with halo (+zero pad to SD_DECL); fused |d| partial (group 0)
    const int span = TILE + 2 * H;
    float wsum = 0.f;
    for (int j = tid; j < SD_DECL; j += THREADS) {
        int g = tile0 - H + j;
        float v = 0.f;
        if (j < span && g >= 0 && g < L_TOTAL) v = o[g] - t[g];
        sd[j] = v;
        if (gy == 0 && j >= H && j < H + TILE && g < L_TOTAL) wsum += fabsf(v);
    }
    __syncthreads();

    const int base = H + tid * RBLK;
    const int gi0  = tile0 + tid * RBLK;

    float csum;
    if      (gy == 0) csum = do_group<1, 19>(sd, base, gi0);
    else if (gy == 1) csum = do_group<19, 26>(sd, base, gi0);
    else if (gy == 2) csum = do_group<26, 32>(sd, base, gi0);
    else              csum = do_group<32, 37>(sd, base, gi0);

    // Block reduction -> per-block partial slots (no atomics, no zeroing)
    csum = warp_sum(csum);
    wsum = warp_sum(wsum);
    const int lane = tid & 31, wrp = tid >> 5;
    if (lane == 0) { s_red[wrp] = csum; s_red[4 + wrp] = wsum; }
    __syncthreads();
    if (tid == 0) {
        g_cwt_part[gy * NBX + blockIdx.x] = s_red[0] + s_red[1] + s_red[2] + s_red[3];
        if (gy == 0)
            g_wave_part[blockIdx.x] = s_red[4] + s_red[5] + s_red[6] + s_red[7];
    }
}

// ---------------------------------------------------------------------------
__global__ void __launch_bounds__(256) finalize_kernel(float* out) {
    __shared__ double rc[256], rw[256];
    const int tid = threadIdx.x;
    double sc = 0.0, sw = 0.0;
    for (int i = tid; i < 4 * NBX; i += 256) sc += (double)g_cwt_part[i];
    for (int i = tid; i < NBX; i += 256)     sw += (double)g_wave_part[i];
    rc[tid] = sc; rw[tid] = sw;
    __syncthreads();
    #pragma unroll
    for (int s = 128; s > 0; s >>= 1) {
        if (tid < s) { rc[tid] += rc[tid + s]; rw[tid] += rw[tid + s]; }
        __syncthreads();
    }
    if (tid == 0) {
        double lw = rw[0] / (double)L_TOTAL;
        double lc = rc[0] / (36.0 * (double)L_TOTAL);
        out[0] = (float)(0.5 * lw + 0.5 * lc);
    }
}

extern "C" void kernel_launch(void* const* d_in, const int* in_sizes, int n_in,
                              void* d_out, int out_size) {
    const float* o = (const float*)d_in[0];
    const float* t = (const float*)d_in[1];
    float* out = (float*)d_out;

    dim3 grid(NBX, 4);
    cwt_kernel<<<grid, THREADS>>>(o, t);
    finalize_kernel<<<1, 256>>>(out);
}

// round 7
// speedup vs baseline: 1.8312x; 1.8312x over previous
#include <cuda_runtime.h>
#include <math.h>

// ---------------------------------------------------------------------------
// CombinedLoss: 0.5*mean|o-t| + 0.5*mean|CWT(o)-CWT(t)| (real morlet, 36 widths)
// CWT(o)-CWT(t) = CWT(d), d=o-t.  'same' conv with reversed kernel ==
// correlation with un-reversed morlet:
//   conv_w[i] = sum_{p=0}^{10w-1} mor_w[p] * d[i + p - 5w]   (zero padded)
// Round 7: packed fma.rn.f32x2 with ZERO repacking: dual shifted shared copies
// give aligned LDS.64 for both pair phases; accumulators packed by tap parity.
// 13 instr / tap-pair (10 FFMA2 + 3 LDS.64); ~1KB loop body (fits L0 I$).
// Coeffs = compile-time __device__ tables; single kernel (last-block reduce).
// ---------------------------------------------------------------------------

#define L_TOTAL   262144
#define THREADS   128
#define RBLK      10
#define TILE      (THREADS * RBLK)                // 1280
#define NBX       ((L_TOTAL + TILE - 1) / TILE)   // 205
#define TOTALB    (4 * NBX)                       // 820
#define SD_DECL   (TILE + 2 * 180 + 24)           // 1664
#define SK_DECL   1712

typedef unsigned long long ull;

__device__ float g_cwt_part[4 * NBX];
__device__ float g_wave_part[NBX];
__device__ unsigned int g_done;                   // zero-init; reset each run

// ======================= constexpr morlet coefficients ======================
__host__ __device__ constexpr double cabs_(double v) { return v < 0.0 ? -v : v; }

__host__ __device__ constexpr double cexp_(double xx) {
    if (xx < -120.0) return 0.0;
    const double LN2_HI = 6.93147180369123816490e-01;
    const double LN2_LO = 1.90821492927058770002e-10;
    const double INV_LN2 = 1.44269504088896338700e+00;
    double nd = xx * INV_LN2;
    int n = (int)(nd >= 0.0 ? nd + 0.5 : nd - 0.5);
    double r = (xx - (double)n * LN2_HI) - (double)n * LN2_LO;
    double term = 1.0, sum = 1.0;
    for (int i = 1; i <= 18; ++i) {
        term *= r / (double)i;
        sum += term;
        if (cabs_(term) < 1e-60) break;
    }
    double p = 1.0, b = (n < 0) ? 0.5 : 2.0;
    int m = (n < 0) ? -n : n;
    while (m) { if (m & 1) p *= b; m >>= 1; if (m) b *= b; }
    return sum * p;
}
__host__ __device__ constexpr double ccos_(double xx) {
    const double PIO2_1  = 1.57079632673412561417e+00;
    const double PIO2_1t = 6.07710050650619224932e-11;
    double ax = xx < 0.0 ? -xx : xx;
    int q = (int)(ax * 0.63661977236758134308 + 0.5);
    double r = (ax - (double)q * PIO2_1) - (double)q * PIO2_1t;
    double r2 = r * r;
    double cs = 1.0, tc = 1.0;
    for (int i = 1; i <= 10; ++i) {
        tc *= -r2 / (double)((2 * i - 1) * (2 * i));
        cs += tc;
        if (cabs_(tc) < 1e-60) break;
    }
    double sn = r, ts = r;
    for (int i = 1; i <= 10; ++i) {
        ts *= -r2 / (double)((2 * i) * (2 * i + 1));
        sn += ts;
        if (cabs_(ts) < 1e-60) break;
    }
    int quad = q & 3;
    return quad == 0 ? cs : quad == 1 ? -sn : quad == 2 ? -cs : sn;
}
__host__ __device__ constexpr double morlet_tap(int w, int p) {
    const double TWO_PI = 6.28318530717958647692;
    const double PI_M025 = 0.75112554446494248286;
    int N = 10 * w;
    double step = (2.0 * TWO_PI) / (double)(N - 1);
    double x = -TWO_PI + (double)p * step;
    double ew = cexp_(-0.5 * (double)(w * w));
    return (ccos_((double)w * x) - ew) * cexp_(-0.5 * x * x) * PI_M025;
}

template<int W> struct Ker { float k[10 * W]; };
template<int W>
__host__ __device__ constexpr Ker<W> make_ker() {
    Ker<W> t{};
    for (int p = 0; p < 10 * W; ++p) t.k[p] = (float)morlet_tap(W, p);
    return t;
}

// One compile-time table per width (proven constexpr scale from Round 6).
template<int W> __device__ const float* kptr();
#define DEFK(W) \
    __device__ const Ker<W> g_k##W = make_ker<W>(); \
    template<> __device__ const float* kptr<W>() { return g_k##W.k; }
DEFK(1)  DEFK(2)  DEFK(3)  DEFK(4)  DEFK(5)  DEFK(6)  DEFK(7)  DEFK(8)
DEFK(9)  DEFK(10) DEFK(11) DEFK(12) DEFK(13) DEFK(14) DEFK(15) DEFK(16)
DEFK(17) DEFK(18) DEFK(19) DEFK(20) DEFK(21) DEFK(22) DEFK(23) DEFK(24)
DEFK(25) DEFK(26) DEFK(27) DEFK(28) DEFK(29) DEFK(30) DEFK(31) DEFK(32)
DEFK(33) DEFK(34) DEFK(35) DEFK(36)
#undef DEFK

// Copy this group's taps (global -> shared), coalesced.
template<int W0, int W1>
__device__ __forceinline__ void copy_group(float* sk, int tid, int koff0) {
    if constexpr (W0 < W1) {
        const float* src = kptr<W0>();
        const int off = 5 * W0 * (W0 - 1) - koff0;
        for (int p = tid; p < 10 * W0; p += THREADS) sk[off + p] = src[p];
        copy_group<W0 + 1, W1>(sk, tid, koff0);
    }
}

// ---------- packed f32x2 helpers ----------
__device__ __forceinline__ void ffma2(ull& d, ull a, ull b) {
    asm("fma.rn.f32x2 %0, %1, %2, %0;" : "+l"(d) : "l"(a), "l"(b));
}
__device__ __forceinline__ float lo_f(ull v) {
    float a, b; asm("mov.b64 {%0, %1}, %2;" : "=f"(a), "=f"(b) : "l"(v)); return a;
}
__device__ __forceinline__ float hi_f(ull v) {
    float a, b; asm("mov.b64 {%0, %1}, %2;" : "=f"(a), "=f"(b) : "l"(v)); return b;
}
__device__ __forceinline__ ull ld64s(const float* p) {
    return *reinterpret_cast<const ull*>(p);
}

// ============================ packed tap engine =============================
// A[r] (r=0..9, packed): lo accumulates even taps, hi odd taps.
// E_j=(x[s0+2j],x[s0+2j+1]) from sd; F_j=(x[s0+2j+1],x[s0+2j+2]) from sd2.
// Odd s0 (odd W): swap base roles so every LDS.64 stays 8B-aligned.
template<int W>
__device__ __forceinline__ float do_width(const float* __restrict__ sd,
                                          const float* __restrict__ sd2,
                                          const float* __restrict__ sk,
                                          int koff0, int base, int gi0) {
    constexpr bool ODD = ((5 * W) & 1) != 0;       // parity of s0
    const int s0 = base - 5 * W;
    const float* bE = ODD ? (sd2 + (s0 - 1)) : (sd + s0);
    const float* bF = ODD ? (sd + (s0 + 1)) : (sd2 + s0);
    const float* bK = sk + (5 * W * (W - 1) - koff0);

    ull E[5], F[5], A[10];
    #pragma unroll
    for (int j = 0; j < 5; ++j) { E[j] = ld64s(bE + 2 * j); F[j] = ld64s(bF + 2 * j); }
    #pragma unroll
    for (int r = 0; r < 10; ++r) A[r] = 0ULL;

    for (int i = 0; i < W; ++i) {                  // 5 tap-pairs per iteration
        #pragma unroll
        for (int j = 0; j < 5; ++j) {
            ull K = ld64s(bK + 2 * j);             // (k_2m, k_2m+1) broadcast
            #pragma unroll
            for (int h = 0; h < 5; ++h) {
                ffma2(A[2 * h],     K, E[(j + h) % 5]);
                ffma2(A[2 * h + 1], K, F[(j + h) % 5]);
            }
            E[j] = ld64s(bE + 2 * j + 10);         // pair m+5 refill
            F[j] = ld64s(bF + 2 * j + 10);
        }
        bE += 10; bF += 10; bK += 10;
    }

    float s = 0.f;
    #pragma unroll
    for (int r = 0; r < 10; ++r)
        if (gi0 + r < L_TOTAL) s += fabsf(lo_f(A[r]) + hi_f(A[r]));
    return s;
}

template<int W0, int W1>
__device__ __forceinline__ float do_group(const float* __restrict__ sd,
                                          const float* __restrict__ sd2,
                                          const float* __restrict__ sk,
                                          int koff0, int base, int gi0) {
    if constexpr (W0 >= W1) { return 0.f; }
    else {
        return do_width<W0>(sd, sd2, sk, koff0, base, gi0)
             + do_group<W0 + 1, W1>(sd, sd2, sk, koff0, base, gi0);
    }
}

__device__ __forceinline__ float warp_sum(float v) {
    #pragma unroll
    for (int o = 16; o > 0; o >>= 1) v += __shfl_xor_sync(0xFFFFFFFFu, v, o);
    return v;
}

// ---------------------------------------------------------------------------
__global__ void __launch_bounds__(THREADS)
cwt_kernel(const float* __restrict__ o, const float* __restrict__ t,
           float* __restrict__ out) {
    __shared__ __align__(8) float sd [SD_DECL];
    __shared__ __align__(8) float sd2[SD_DECL];
    __shared__ __align__(8) float sk [SK_DECL];
    __shared__ float s_red[8];
    __shared__ unsigned s_last;

    const int gy = blockIdx.y;
    const int H  = (gy == 0) ? 90 : (gy == 1) ? 126 : (gy == 2) ? 156 : 180;
    const int tile0 = blockIdx.x * TILE;
    const int tid = threadIdx.x;

    // Diff with halo, zero-padded to SD_DECL; shifted copy; fused |d| (gy 0)
    const int span = TILE + 2 * H;
    float wsum = 0.f;
    for (int j = tid; j < SD_DECL; j += THREADS) {
        int g = tile0 - H + j;
        float v = 0.f;
        if (j < span && g >= 0 && g < L_TOTAL) v = o[g] - t[g];
        sd[j] = v;
        if (j > 0) sd2[j - 1] = v;
        if (j == SD_DECL - 1) sd2[SD_DECL - 1] = 0.f;
        if (gy == 0 && j >= H && j < H + TILE && g < L_TOTAL) wsum += fabsf(v);
    }

    // This group's coefficient table -> shared
    int koff0;
    if      (gy == 0) { koff0 = 0;    copy_group<1, 19>(sk, tid, koff0); }
    else if (gy == 1) { koff0 = 1710; copy_group<19, 26>(sk, tid, koff0); }
    else if (gy == 2) { koff0 = 3250; copy_group<26, 32>(sk, tid, koff0); }
    else              { koff0 = 4960; copy_group<32, 37>(sk, tid, koff0); }
    __syncthreads();

    const int base = H + tid * RBLK;
    const int gi0  = tile0 + tid * RBLK;

    float csum;
    if      (gy == 0) csum = do_group<1, 19>(sd, sd2, sk, 0,    base, gi0);
    else if (gy == 1) csum = do_group<19, 26>(sd, sd2, sk, 1710, base, gi0);
    else if (gy == 2) csum = do_group<26, 32>(sd, sd2, sk, 3250, base, gi0);
    else              csum = do_group<32, 37>(sd, sd2, sk, 4960, base, gi0);

    // Block reduction -> per-block partial slots
    csum = warp_sum(csum);
    wsum = warp_sum(wsum);
    const int lane = tid & 31, wrp = tid >> 5;
    if (lane == 0) { s_red[wrp] = csum; s_red[4 + wrp] = wsum; }
    __syncthreads();
    if (tid == 0) {
        g_cwt_part[gy * NBX + blockIdx.x] = s_red[0] + s_red[1] + s_red[2] + s_red[3];
        if (gy == 0)
            g_wave_part[blockIdx.x] = s_red[4] + s_red[5] + s_red[6] + s_red[7];
    }

    // Last block finalizes (saves a kernel launch)
    __threadfence();
    if (tid == 0) {
        unsigned old = atomicAdd(&g_done, 1u);
        s_last = (old == TOTALB - 1) ? 1u : 0u;
    }
    __syncthreads();
    if (s_last) {
        double sc = 0.0, sw = 0.0;
        for (int i = tid; i < 4 * NBX; i += THREADS) sc += (double)__ldcg(&g_cwt_part[i]);
        for (int i = tid; i < NBX; i += THREADS)     sw += (double)__ldcg(&g_wave_part[i]);
        double* rc = reinterpret_cast<double*>(sd);
        double* rw = reinterpret_cast<double*>(sd) + THREADS;
        rc[tid] = sc; rw[tid] = sw;
        __syncthreads();
        #pragma unroll
        for (int s = THREADS / 2; s > 0; s >>= 1) {
            if (tid < s) { rc[tid] += rc[tid + s]; rw[tid] += rw[tid + s]; }
            __syncthreads();
        }
        if (tid == 0) {
            double lw = rw[0] / (double)L_TOTAL;
            double lc = rc[0] / (36.0 * (double)L_TOTAL);
            out[0] = (float)(0.5 * lw + 0.5 * lc);
            g_done = 0;                            // reset for next replay
        }
    }
}

extern "C" void kernel_launch(void* const* d_in, const int* in_sizes, int n_in,
                              void* d_out, int out_size) {
    const float* o = (const float*)d_in[0];
    const float* t = (const float*)d_in[1];
    float* out = (float*)d_out;

    dim3 grid(NBX, 4);
    cwt_kernel<<<grid, THREADS>>>(o, t, out);
}

// round 8
// speedup vs baseline: 2.4917x; 1.3607x over previous
#include <cuda_runtime.h>
#include <math.h>

// ---------------------------------------------------------------------------
// CombinedLoss: 0.5*mean|o-t| + 0.5*mean|CWT(o)-CWT(t)| (real morlet, 36 widths)
// CWT(o)-CWT(t) = CWT(d), d=o-t.  'same' conv with reversed kernel ==
// correlation with un-reversed morlet:
//   conv_w[i] = sum_{p=0}^{10w-1} mor_w[p] * d[i + p - 5w]   (zero padded)
// Round 8: packed fma.rn.f32x2 engine (proven 2x math) with a RUNTIME-W inner
// loop (tiny body, no full unroll), reg cap for occupancy, K-prefetch.
// ---------------------------------------------------------------------------

#define L_TOTAL   262144
#define THREADS   128
#define RBLK      10
#define TILE      (THREADS * RBLK)                // 1280
#define NBX       ((L_TOTAL + TILE - 1) / TILE)   // 205
#define TOTALB    (4 * NBX)                       // 820
#define SD_DECL   (TILE + 2 * 180 + 24)           // 1664
#define SK_DECL   1712

typedef unsigned long long ull;

__device__ float g_cwt_part[4 * NBX];
__device__ float g_wave_part[NBX];
__device__ unsigned int g_done;                   // zero-init; reset each run

// ======================= constexpr morlet coefficients ======================
__host__ __device__ constexpr double cabs_(double v) { return v < 0.0 ? -v : v; }

__host__ __device__ constexpr double cexp_(double xx) {
    if (xx < -120.0) return 0.0;
    const double LN2_HI = 6.93147180369123816490e-01;
    const double LN2_LO = 1.90821492927058770002e-10;
    const double INV_LN2 = 1.44269504088896338700e+00;
    double nd = xx * INV_LN2;
    int n = (int)(nd >= 0.0 ? nd + 0.5 : nd - 0.5);
    double r = (xx - (double)n * LN2_HI) - (double)n * LN2_LO;
    double term = 1.0, sum = 1.0;
    for (int i = 1; i <= 18; ++i) {
        term *= r / (double)i;
        sum += term;
        if (cabs_(term) < 1e-60) break;
    }
    double p = 1.0, b = (n < 0) ? 0.5 : 2.0;
    int m = (n < 0) ? -n : n;
    while (m) { if (m & 1) p *= b; m >>= 1; if (m) b *= b; }
    return sum * p;
}
__host__ __device__ constexpr double ccos_(double xx) {
    const double PIO2_1  = 1.57079632673412561417e+00;
    const double PIO2_1t = 6.07710050650619224932e-11;
    double ax = xx < 0.0 ? -xx : xx;
    int q = (int)(ax * 0.63661977236758134308 + 0.5);
    double r = (ax - (double)q * PIO2_1) - (double)q * PIO2_1t;
    double r2 = r * r;
    double cs = 1.0, tc = 1.0;
    for (int i = 1; i <= 10; ++i) {
        tc *= -r2 / (double)((2 * i - 1) * (2 * i));
        cs += tc;
        if (cabs_(tc) < 1e-60) break;
    }
    double sn = r, ts = r;
    for (int i = 1; i <= 10; ++i) {
        ts *= -r2 / (double)((2 * i) * (2 * i + 1));
        sn += ts;
        if (cabs_(ts) < 1e-60) break;
    }
    int quad = q & 3;
    return quad == 0 ? cs : quad == 1 ? -sn : quad == 2 ? -cs : sn;
}
__host__ __device__ constexpr double morlet_tap(int w, int p) {
    const double TWO_PI = 6.28318530717958647692;
    const double PI_M025 = 0.75112554446494248286;
    int N = 10 * w;
    double step = (2.0 * TWO_PI) / (double)(N - 1);
    double x = -TWO_PI + (double)p * step;
    double ew = cexp_(-0.5 * (double)(w * w));
    return (ccos_((double)w * x) - ew) * cexp_(-0.5 * x * x) * PI_M025;
}

template<int W> struct Ker { float k[10 * W]; };
template<int W>
__host__ __device__ constexpr Ker<W> make_ker() {
    Ker<W> t{};
    for (int p = 0; p < 10 * W; ++p) t.k[p] = (float)morlet_tap(W, p);
    return t;
}

template<int W> __device__ const float* kptr();
#define DEFK(W) \
    __device__ const Ker<W> g_k##W = make_ker<W>(); \
    template<> __device__ const float* kptr<W>() { return g_k##W.k; }
DEFK(1)  DEFK(2)  DEFK(3)  DEFK(4)  DEFK(5)  DEFK(6)  DEFK(7)  DEFK(8)
DEFK(9)  DEFK(10) DEFK(11) DEFK(12) DEFK(13) DEFK(14) DEFK(15) DEFK(16)
DEFK(17) DEFK(18) DEFK(19) DEFK(20) DEFK(21) DEFK(22) DEFK(23) DEFK(24)
DEFK(25) DEFK(26) DEFK(27) DEFK(28) DEFK(29) DEFK(30) DEFK(31) DEFK(32)
DEFK(33) DEFK(34) DEFK(35) DEFK(36)
#undef DEFK

// Copy this group's taps (global -> shared), coalesced.
template<int W0, int W1>
__device__ __forceinline__ void copy_group(float* sk, int tid, int koff0) {
    if constexpr (W0 < W1) {
        const float* src = kptr<W0>();
        const int off = 5 * W0 * (W0 - 1) - koff0;
        for (int p = tid; p < 10 * W0; p += THREADS) sk[off + p] = src[p];
        copy_group<W0 + 1, W1>(sk, tid, koff0);
    }
}

// ---------- packed f32x2 helpers ----------
__device__ __forceinline__ void ffma2(ull& d, ull a, ull b) {
    asm("fma.rn.f32x2 %0, %1, %2, %0;" : "+l"(d) : "l"(a), "l"(b));
}
__device__ __forceinline__ float lo_f(ull v) {
    float a, b; asm("mov.b64 {%0, %1}, %2;" : "=f"(a), "=f"(b) : "l"(v)); return a;
}
__device__ __forceinline__ float hi_f(ull v) {
    float a, b; asm("mov.b64 {%0, %1}, %2;" : "=f"(a), "=f"(b) : "l"(v)); return b;
}
__device__ __forceinline__ ull ld64s(const float* p) {
    return *reinterpret_cast<const ull*>(p);
}

// ============================ packed tap engine =============================
// Runtime W: one tiny loop body for all widths. A[r].lo accumulates even taps,
// A[r].hi odd taps for output r. E pairs from sd, F pairs from sd2 (shifted
// copy) -> every access is an aligned LDS.64, zero repacking. K prefetched one
// step ahead (13-instr load->use distance).
__device__ float do_width_rt(const float* __restrict__ bE,
                             const float* __restrict__ bF,
                             const float* __restrict__ bK,
                             int W, int gi0) {
    ull E[5], F[5], A[10];
    #pragma unroll
    for (int j = 0; j < 5; ++j) { E[j] = ld64s(bE + 2 * j); F[j] = ld64s(bF + 2 * j); }
    #pragma unroll
    for (int r = 0; r < 10; ++r) A[r] = 0ULL;

    ull K = ld64s(bK);
    #pragma unroll 1
    for (int i = 0; i < W; ++i) {                  // 5 tap-pairs / iteration
        #pragma unroll
        for (int j = 0; j < 5; ++j) {
            ull Kn = ld64s(bK + 2 * (j + 1));      // prefetch next pair coeff
            #pragma unroll
            for (int h = 0; h < 5; ++h) {
                ffma2(A[2 * h],     K, E[(j + h) % 5]);
                ffma2(A[2 * h + 1], K, F[(j + h) % 5]);
            }
            E[j] = ld64s(bE + 2 * j + 10);         // pair m+5 refill
            F[j] = ld64s(bF + 2 * j + 10);
            K = Kn;
        }
        bE += 10; bF += 10; bK += 10;
    }

    float s = 0.f;
    #pragma unroll
    for (int r = 0; r < 10; ++r)
        if (gi0 + r < L_TOTAL) s += fabsf(lo_f(A[r]) + hi_f(A[r]));
    return s;
}

__device__ __forceinline__ float warp_sum(float v) {
    #pragma unroll
    for (int o = 16; o > 0; o >>= 1) v += __shfl_xor_sync(0xFFFFFFFFu, v, o);
    return v;
}

// ---------------------------------------------------------------------------
__global__ void __launch_bounds__(THREADS, 6)
cwt_kernel(const float* __restrict__ o, const float* __restrict__ t,
           float* __restrict__ out) {
    __shared__ __align__(8) float sd [SD_DECL];
    __shared__ __align__(8) float sd2[SD_DECL];
    __shared__ __align__(8) float sk [SK_DECL];
    __shared__ float s_red[8];
    __shared__ unsigned s_last;

    const int gy = blockIdx.y;
    const int H  = (gy == 0) ? 90 : (gy == 1) ? 126 : (gy == 2) ? 156 : 180;
    const int w0 = (gy == 0) ? 1 : (gy == 1) ? 19 : (gy == 2) ? 26 : 32;
    const int w1 = (gy == 0) ? 19 : (gy == 1) ? 26 : (gy == 2) ? 32 : 37;
    const int tile0 = blockIdx.x * TILE;
    const int tid = threadIdx.x;

    // Diff with halo, zero-padded to SD_DECL; shifted copy; fused |d| (gy 0)
    const int span = TILE + 2 * H;
    float wsum = 0.f;
    for (int j = tid; j < SD_DECL; j += THREADS) {
        int g = tile0 - H + j;
        float v = 0.f;
        if (j < span && g >= 0 && g < L_TOTAL) v = o[g] - t[g];
        sd[j] = v;
        if (j > 0) sd2[j - 1] = v;
        if (j == SD_DECL - 1) sd2[SD_DECL - 1] = 0.f;
        if (gy == 0 && j >= H && j < H + TILE && g < L_TOTAL) wsum += fabsf(v);
    }

    // This group's coefficient table -> shared
    int koff0;
    if      (gy == 0) { koff0 = 0;    copy_group<1, 19>(sk, tid, koff0); }
    else if (gy == 1) { koff0 = 1710; copy_group<19, 26>(sk, tid, koff0); }
    else if (gy == 2) { koff0 = 3250; copy_group<26, 32>(sk, tid, koff0); }
    else              { koff0 = 4960; copy_group<32, 37>(sk, tid, koff0); }
    __syncthreads();

    const int base = H + tid * RBLK;
    const int gi0  = tile0 + tid * RBLK;

    float csum = 0.f;
    #pragma unroll 1
    for (int w = w0; w < w1; ++w) {
        const int s0 = base - 5 * w;
        const int odd = w & 1;                     // parity of s0 == parity of 5w
        const float* bE = odd ? (sd2 + (s0 - 1)) : (sd + s0);
        const float* bF = odd ? (sd + (s0 + 1)) : (sd2 + s0);
        const float* bK = sk + (5 * w * (w - 1) - koff0);
        csum += do_width_rt(bE, bF, bK, w, gi0);
    }

    // Block reduction -> per-block partial slots
    csum = warp_sum(csum);
    wsum = warp_sum(wsum);
    const int lane = tid & 31, wrp = tid >> 5;
    if (lane == 0) { s_red[wrp] = csum; s_red[4 + wrp] = wsum; }
    __syncthreads();
    if (tid == 0) {
        g_cwt_part[gy * NBX + blockIdx.x] = s_red[0] + s_red[1] + s_red[2] + s_red[3];
        if (gy == 0)
            g_wave_part[blockIdx.x] = s_red[4] + s_red[5] + s_red[6] + s_red[7];
    }

    // Last block finalizes (saves a kernel launch)
    __threadfence();
    if (tid == 0) {
        unsigned old = atomicAdd(&g_done, 1u);
        s_last = (old == TOTALB - 1) ? 1u : 0u;
    }
    __syncthreads();
    if (s_last) {
        double sc = 0.0, sw = 0.0;
        for (int i = tid; i < 4 * NBX; i += THREADS) sc += (double)__ldcg(&g_cwt_part[i]);
        for (int i = tid; i < NBX; i += THREADS)     sw += (double)__ldcg(&g_wave_part[i]);
        double* rc = reinterpret_cast<double*>(sd);
        double* rw = reinterpret_cast<double*>(sd) + THREADS;
        rc[tid] = sc; rw[tid] = sw;
        __syncthreads();
        #pragma unroll
        for (int s = THREADS / 2; s > 0; s >>= 1) {
            if (tid < s) { rc[tid] += rc[tid + s]; rw[tid] += rw[tid + s]; }
            __syncthreads();
        }
        if (tid == 0) {
            double lw = rw[0] / (double)L_TOTAL;
            double lc = rc[0] / (36.0 * (double)L_TOTAL);
            out[0] = (float)(0.5 * lw + 0.5 * lc);
            g_done = 0;                            // reset for next replay
        }
    }
}

extern "C" void kernel_launch(void* const* d_in, const int* in_sizes, int n_in,
                              void* d_out, int out_size) {
    const float* o = (const float*)d_in[0];
    const float* t = (const float*)d_in[1];
    float* out = (float*)d_out;

    dim3 grid(NBX, 4);
    cwt_kernel<<<grid, THREADS>>>(o, t, out);
}